// round 3
// baseline (speedup 1.0000x reference)
#include <cuda_runtime.h>

// Problem constants (match reference_code)
#define NN 4096   // batch
#define DD 8192   // feature dim
#define KE 0.14426950408889634f   // log2(e) / tau, tau = 10
#define RPB 4     // rows per block

__device__ __forceinline__ float ex2f(float x) {
    float y;
    asm("ex2.approx.ftz.f32 %0, %1;" : "=f"(y) : "f"(x));
    return y;
}

__global__ __launch_bounds__(256) void supcon_kernel(const float* __restrict__ emb,
                                                     const long long* __restrict__ labels,
                                                     float* __restrict__ out) {
    __shared__ __align__(16) unsigned char slab[NN];
    __shared__ float s_a[8], s_b[8];
    __shared__ int   s_c[8];

    const int tid  = threadIdx.x;
    const int lane = tid & 31;
    const int wid  = tid >> 5;

    // Build the 4096-entry uint8 label table from the int64 input (self-contained,
    // no device-global scratch). 2048 longlong2 loads spread over 256 threads.
    const longlong2* __restrict__ L2v = (const longlong2*)labels;
    #pragma unroll
    for (int k = 0; k < 8; k++) {
        const int idx = tid + k * 256;
        const longlong2 v = L2v[idx];
        slab[2 * idx + 0] = (unsigned char)v.x;
        slab[2 * idx + 1] = (unsigned char)v.y;
    }
    __syncthreads();

    float termAcc = 0.0f;   // meaningful on tid 0 only

    #pragma unroll 1
    for (int r = 0; r < RPB; r++) {
        const int i = blockIdx.x * RPB + r;
        const unsigned char myl = slab[i];
        const float4* __restrict__ row = (const float4*)(emb + (size_t)i * DD);

        float rowsum = 0.0f;
        float sB     = 0.0f;
        int   cnt    = 0;

        // ---- first half: d in [0, NN): A + masked B ----
        #pragma unroll
        for (int it = 0; it < 4; it++) {
            const int v4 = it * 256 + tid;
            const float4 v = row[v4];
            const uchar4 lb = ((const uchar4*)slab)[v4];
            const int d0 = v4 * 4;

            float a0 = ex2f(v.x * v.x * KE);
            float a1 = ex2f(v.y * v.y * KE);
            float a2 = ex2f(v.z * v.z * KE);
            float a3 = ex2f(v.w * v.w * KE);
            rowsum += (a0 + a1) + (a2 + a3);

            if (lb.x == myl && d0 + 0 != i) { sB += ex2f(a0 * KE); cnt++; }
            if (lb.y == myl && d0 + 1 != i) { sB += ex2f(a1 * KE); cnt++; }
            if (lb.z == myl && d0 + 2 != i) { sB += ex2f(a2 * KE); cnt++; }
            if (lb.w == myl && d0 + 3 != i) { sB += ex2f(a3 * KE); cnt++; }
        }

        // ---- second half: d in [NN, DD): A only ----
        #pragma unroll
        for (int it = 0; it < 4; it++) {
            const int v4 = 1024 + it * 256 + tid;
            const float4 v = row[v4];
            rowsum += (ex2f(v.x * v.x * KE) + ex2f(v.y * v.y * KE)) +
                      (ex2f(v.z * v.z * KE) + ex2f(v.w * v.w * KE));
        }

        // ---- intra-block reduce ----
        #pragma unroll
        for (int o = 16; o > 0; o >>= 1) {
            rowsum += __shfl_down_sync(0xFFFFFFFFu, rowsum, o);
            sB     += __shfl_down_sync(0xFFFFFFFFu, sB, o);
            cnt    += __shfl_down_sync(0xFFFFFFFFu, cnt, o);
        }
        if (lane == 0) { s_a[wid] = rowsum; s_b[wid] = sB; s_c[wid] = cnt; }
        __syncthreads();

        if (tid == 0) {
            float ts = 0.0f, tb = 0.0f;
            int   tc = 0;
            #pragma unroll
            for (int w = 0; w < 8; w++) { ts += s_a[w]; tb += s_b[w]; tc += s_c[w]; }
            const float xd    = emb[(size_t)i * DD + i];
            const float denom = ts - ex2f(xd * xd * KE);
            termAcc += __logf(tb / (denom * (float)tc));
        }
        __syncthreads();   // protect s_a/s_b/s_c reuse on the next row
    }

    if (tid == 0) atomicAdd(out, termAcc);
}

extern "C" void kernel_launch(void* const* d_in, const int* in_sizes, int n_in,
                              void* d_out, int out_size) {
    const float*     emb    = (const float*)d_in[0];
    const long long* labels = (const long long*)d_in[1];
    float*           out    = (float*)d_out;

    cudaMemsetAsync(out, 0, sizeof(float));
    supcon_kernel<<<NN / RPB, 256>>>(emb, labels, out);
}

// round 5
// speedup vs baseline: 1.2054x; 1.2054x over previous
#include <cuda_runtime.h>

// Problem constants (match reference_code)
#define NN 4096   // batch
#define DD 8192   // feature dim
#define KE 0.14426950408889634f   // log2(e) / tau, tau = 10

__device__ __forceinline__ float ex2f(float x) {
    float y;
    asm("ex2.approx.ftz.f32 %0, %1;" : "=f"(y) : "f"(x));
    return y;
}

__global__ __launch_bounds__(256) void supcon_kernel(const float* __restrict__ emb,
                                                     const long long* __restrict__ labels,
                                                     float* __restrict__ out) {
    __shared__ __align__(16) unsigned char slab[NN];
    __shared__ float sAsum[8], sAB[8], sBsum[8], sBB[8];
    __shared__ int   sAc[8], sBc[8];
    __shared__ float s_term[2];

    const int tid  = threadIdx.x;
    const int lane = tid & 31;
    const int wid  = tid >> 5;

    // Two rows handled by this block
    const int iA = blockIdx.x * 2;
    const int iB = iA + 1;

    // Build 4096-entry uint8 label table from int64 input (proven in R2)
    const longlong2* __restrict__ L2v = (const longlong2*)labels;
    #pragma unroll
    for (int k = 0; k < 8; k++) {
        const int idx = tid + k * 256;
        const longlong2 v = L2v[idx];
        slab[2 * idx + 0] = (unsigned char)v.x;
        slab[2 * idx + 1] = (unsigned char)v.y;
    }
    __syncthreads();

    const unsigned char lA = slab[iA];
    const unsigned char lB = slab[iB];
    const float4* __restrict__ rowA = (const float4*)(emb + (size_t)iA * DD);
    const float4* __restrict__ rowB = (const float4*)(emb + (size_t)iB * DD);

    float sumA = 0.0f, sumB = 0.0f;   // denominators (row sums of A)
    float bA = 0.0f, bB = 0.0f;       // masked numerator sums
    int   cA = 0, cB = 0;             // masked counts

    // ---- first half: d in [0, NN): A + masked B, both rows interleaved ----
    #pragma unroll
    for (int it = 0; it < 4; it++) {
        const int v4 = it * 256 + tid;
        const int d0 = v4 * 4;
        const float4 va = rowA[v4];
        const float4 vb = rowB[v4];
        const uchar4 lb = ((const uchar4*)slab)[v4];

        float a0 = ex2f(va.x * va.x * KE);
        float a1 = ex2f(va.y * va.y * KE);
        float a2 = ex2f(va.z * va.z * KE);
        float a3 = ex2f(va.w * va.w * KE);
        sumA += (a0 + a1) + (a2 + a3);

        float b0 = ex2f(vb.x * vb.x * KE);
        float b1 = ex2f(vb.y * vb.y * KE);
        float b2 = ex2f(vb.z * vb.z * KE);
        float b3 = ex2f(vb.w * vb.w * KE);
        sumB += (b0 + b1) + (b2 + b3);

        if (lb.x == lA && d0 + 0 != iA) { bA += ex2f(a0 * KE); cA++; }
        if (lb.y == lA && d0 + 1 != iA) { bA += ex2f(a1 * KE); cA++; }
        if (lb.z == lA && d0 + 2 != iA) { bA += ex2f(a2 * KE); cA++; }
        if (lb.w == lA && d0 + 3 != iA) { bA += ex2f(a3 * KE); cA++; }

        if (lb.x == lB && d0 + 0 != iB) { bB += ex2f(b0 * KE); cB++; }
        if (lb.y == lB && d0 + 1 != iB) { bB += ex2f(b1 * KE); cB++; }
        if (lb.z == lB && d0 + 2 != iB) { bB += ex2f(b2 * KE); cB++; }
        if (lb.w == lB && d0 + 3 != iB) { bB += ex2f(b3 * KE); cB++; }
    }

    // ---- second half: d in [NN, DD): A only, both rows interleaved ----
    #pragma unroll
    for (int it = 0; it < 4; it++) {
        const int v4 = 1024 + it * 256 + tid;
        const float4 va = rowA[v4];
        const float4 vb = rowB[v4];
        sumA += (ex2f(va.x * va.x * KE) + ex2f(va.y * va.y * KE)) +
                (ex2f(va.z * va.z * KE) + ex2f(va.w * va.w * KE));
        sumB += (ex2f(vb.x * vb.x * KE) + ex2f(vb.y * vb.y * KE)) +
                (ex2f(vb.z * vb.z * KE) + ex2f(vb.w * vb.w * KE));
    }

    // ---- intra-block reduce (explicit, one sync) ----
    #pragma unroll
    for (int o = 16; o > 0; o >>= 1) {
        sumA += __shfl_down_sync(0xFFFFFFFFu, sumA, o);
        bA   += __shfl_down_sync(0xFFFFFFFFu, bA, o);
        cA   += __shfl_down_sync(0xFFFFFFFFu, cA, o);
        sumB += __shfl_down_sync(0xFFFFFFFFu, sumB, o);
        bB   += __shfl_down_sync(0xFFFFFFFFu, bB, o);
        cB   += __shfl_down_sync(0xFFFFFFFFu, cB, o);
    }
    if (lane == 0) {
        sAsum[wid] = sumA; sAB[wid] = bA; sAc[wid] = cA;
        sBsum[wid] = sumB; sBB[wid] = bB; sBc[wid] = cB;
    }
    __syncthreads();

    if (tid == 0) {
        float tsA = 0.0f, tbA = 0.0f;
        int   tcA = 0;
        #pragma unroll
        for (int w = 0; w < 8; w++) { tsA += sAsum[w]; tbA += sAB[w]; tcA += sAc[w]; }
        const float xdA = emb[(size_t)iA * DD + iA];
        const float dnA = tsA - ex2f(xdA * xdA * KE);
        s_term[0] = __logf(tbA / (dnA * (float)tcA));
    }
    if (tid == 32) {
        float tsB = 0.0f, tbB = 0.0f;
        int   tcB = 0;
        #pragma unroll
        for (int w = 0; w < 8; w++) { tsB += sBsum[w]; tbB += sBB[w]; tcB += sBc[w]; }
        const float xdB = emb[(size_t)iB * DD + iB];
        const float dnB = tsB - ex2f(xdB * xdB * KE);
        s_term[1] = __logf(tbB / (dnB * (float)tcB));
    }
    __syncthreads();

    if (tid == 0) atomicAdd(out, s_term[0] + s_term[1]);
}

extern "C" void kernel_launch(void* const* d_in, const int* in_sizes, int n_in,
                              void* d_out, int out_size) {
    const float*     emb    = (const float*)d_in[0];
    const long long* labels = (const long long*)d_in[1];
    float*           out    = (float*)d_out;

    cudaMemsetAsync(out, 0, sizeof(float));
    supcon_kernel<<<NN / 2, 256>>>(emb, labels, out);
}